// round 4
// baseline (speedup 1.0000x reference)
#include <cuda_runtime.h>
#include <math.h>

// Problem constants
#define BB   2
#define SS   2048
#define DD   2048
#define HH   16
#define KVH  4
#define HD   128
#define MROWS (BB * SS)        // 4096
#define KVD  (KVH * HD)        // 512

// Scratch buffers (device globals: allocation-free rule)
__device__ float g_Q[(size_t)MROWS * DD];   // [B,S,H,HD]
__device__ float g_K[(size_t)MROWS * KVD];  // [B,S,KVH,HD]
__device__ float g_V[(size_t)MROWS * KVD];
__device__ float g_O[(size_t)MROWS * DD];

// ---------------------------------------------------------------------------
// Tiled fp32 SGEMM: C[M,N] = A[M,K] @ B[K,N], all row-major.
// BM=BN=128, BK=16, 256 threads, 8x8 per-thread microtile.
// Requires M%128==0, N%128==0, K%16==0 (true for all four calls).
// ---------------------------------------------------------------------------
__global__ __launch_bounds__(256) void sgemm128(const float* __restrict__ A,
                                                const float* __restrict__ B,
                                                float* __restrict__ C,
                                                int M, int N, int K) {
    __shared__ float As[16][132];  // transposed A tile, padded
    __shared__ float Bs[16][128];

    const int tid = threadIdx.x;
    const int bm = blockIdx.y, bn = blockIdx.x;
    const int tr = (tid >> 4) << 3;   // 0..120, step 8
    const int tc = (tid & 15) << 3;

    const int arow = tid >> 2;        // 0..63
    const int acol = (tid & 3) << 2;  // 0,4,8,12
    const int brow = tid >> 5;        // 0..7
    const int bcol = (tid & 31) << 2; // 0..124

    const float* Ab = A + (size_t)(bm * 128) * K;
    const float* Bb = B + bn * 128;

    float acc[8][8];
#pragma unroll
    for (int i = 0; i < 8; i++)
#pragma unroll
        for (int j = 0; j < 8; j++) acc[i][j] = 0.f;

    for (int k0 = 0; k0 < K; k0 += 16) {
        float4 a0 = *(const float4*)(Ab + (size_t)arow * K + k0 + acol);
        float4 a1 = *(const float4*)(Ab + (size_t)(arow + 64) * K + k0 + acol);
        float4 b0 = *(const float4*)(Bb + (size_t)(k0 + brow) * N + bcol);
        float4 b1 = *(const float4*)(Bb + (size_t)(k0 + brow + 8) * N + bcol);

        __syncthreads();
        As[acol + 0][arow] = a0.x; As[acol + 1][arow] = a0.y;
        As[acol + 2][arow] = a0.z; As[acol + 3][arow] = a0.w;
        As[acol + 0][arow + 64] = a1.x; As[acol + 1][arow + 64] = a1.y;
        As[acol + 2][arow + 64] = a1.z; As[acol + 3][arow + 64] = a1.w;
        *(float4*)&Bs[brow][bcol]     = b0;
        *(float4*)&Bs[brow + 8][bcol] = b1;
        __syncthreads();

#pragma unroll
        for (int k = 0; k < 16; k++) {
            float ra[8], rb[8];
            *(float4*)&ra[0] = *(const float4*)&As[k][tr];
            *(float4*)&ra[4] = *(const float4*)&As[k][tr + 4];
            *(float4*)&rb[0] = *(const float4*)&Bs[k][tc];
            *(float4*)&rb[4] = *(const float4*)&Bs[k][tc + 4];
#pragma unroll
            for (int i = 0; i < 8; i++)
#pragma unroll
                for (int j = 0; j < 8; j++)
                    acc[i][j] += ra[i] * rb[j];
        }
    }

    float* Cb = C + (size_t)(bm * 128 + tr) * N + bn * 128 + tc;
#pragma unroll
    for (int i = 0; i < 8; i++) {
        *(float4*)(Cb + (size_t)i * N)     = make_float4(acc[i][0], acc[i][1], acc[i][2], acc[i][3]);
        *(float4*)(Cb + (size_t)i * N + 4) = make_float4(acc[i][4], acc[i][5], acc[i][6], acc[i][7]);
    }
}

// ---------------------------------------------------------------------------
// RoPE applied in-place to Q (heads 0..15) and K (heads 16..19).
// grid (B*S, H+KVH), block 128.
// out[i]    = x[2i]*cos - x[2i+1]*sin
// out[i+64] = x[2i+1]*cos + x[2i]*sin
// ---------------------------------------------------------------------------
__global__ __launch_bounds__(128) void rope_kernel(float* __restrict__ Q,
                                                   float* __restrict__ Kb,
                                                   const float* __restrict__ cosp,
                                                   const float* __restrict__ sinp) {
    const int bs = blockIdx.x;            // 0..4095
    const int hy = blockIdx.y;            // 0..19
    const int s  = bs & (SS - 1);

    __shared__ float x[HD];
    float* ptr;
    if (hy < HH) ptr = Q  + (size_t)bs * DD  + hy * HD;
    else         ptr = Kb + (size_t)bs * KVD + (hy - HH) * HD;

    x[threadIdx.x] = ptr[threadIdx.x];
    __syncthreads();
    if (threadIdx.x < 64) {
        const int i = threadIdx.x;
        const float c  = cosp[s * 64 + i];
        const float sn = sinp[s * 64 + i];
        const float p1 = x[2 * i], p2 = x[2 * i + 1];
        ptr[i]      = p1 * c - p2 * sn;
        ptr[i + 64] = p2 * c + p1 * sn;
    }
}

// ---------------------------------------------------------------------------
// fp32 causal flash attention with GQA (q head h -> kv head h/4).
// Block: 256 threads (ty=tid/16 in 0..15 -> 4 rows each; tx=tid%16).
// Q tile 64 rows; K/V tiles 64 rows. Online softmax.
// Dynamic smem: Qts[128][68] + Kts[128][68] + Vs[64][128] + Pts[64][68].
// ---------------------------------------------------------------------------
#define FLASH_SMEM ((128 * 68 * 2 + 64 * 128 + 64 * 68) * 4)

__global__ __launch_bounds__(256) void flash_attn(const float* __restrict__ Q,
                                                  const float* __restrict__ Kg,
                                                  const float* __restrict__ Vg,
                                                  float* __restrict__ O) {
    extern __shared__ float sm[];
    float* Qts = sm;                 // [128][68]  (d-major, transposed)
    float* Kts = sm + 128 * 68;      // [128][68]
    float* Vs  = Kts + 128 * 68;     // [64][128]
    float* Pts = Vs + 64 * 128;      // [64][68]   (k-major)

    const int qt = blockIdx.x, h = blockIdx.y, b = blockIdx.z;
    const int kvh = h >> 2;
    const int tid = threadIdx.x;
    const int tx = tid & 15, ty = tid >> 4;
    const int qs = qt << 6;
    const float scale = 0.088388347648318447f;  // 1/sqrt(128)

    // Load Q tile transposed into smem
    for (int idx = tid; idx < 64 * 32; idx += 256) {
        const int r = idx >> 5, d4 = (idx & 31) << 2;
        float4 v = *(const float4*)(Q + (size_t)((b << 11) + qs + r) * DD + (h << 7) + d4);
        Qts[(d4 + 0) * 68 + r] = v.x; Qts[(d4 + 1) * 68 + r] = v.y;
        Qts[(d4 + 2) * 68 + r] = v.z; Qts[(d4 + 3) * 68 + r] = v.w;
    }

    float m_run[4], l_run[4], oa[4][8];
#pragma unroll
    for (int i = 0; i < 4; i++) {
        m_run[i] = -1e30f; l_run[i] = 0.f;
#pragma unroll
        for (int j = 0; j < 8; j++) oa[i][j] = 0.f;
    }

    for (int t = 0; t <= qt; t++) {
        const int ks = t << 6;
        __syncthreads();  // prior iteration's smem consumers done
        for (int idx = tid; idx < 64 * 32; idx += 256) {
            const int r = idx >> 5, d4 = (idx & 31) << 2;
            const size_t gro = (size_t)((b << 11) + ks + r) * KVD + (kvh << 7) + d4;
            float4 kv = *(const float4*)(Kg + gro);
            Kts[(d4 + 0) * 68 + r] = kv.x; Kts[(d4 + 1) * 68 + r] = kv.y;
            Kts[(d4 + 2) * 68 + r] = kv.z; Kts[(d4 + 3) * 68 + r] = kv.w;
            float4 vv = *(const float4*)(Vg + gro);
            *(float4*)&Vs[r * 128 + d4] = vv;
        }
        __syncthreads();

        // S = Q K^T  (4x4 per thread)
        float s[4][4];
#pragma unroll
        for (int i = 0; i < 4; i++)
#pragma unroll
            for (int j = 0; j < 4; j++) s[i][j] = 0.f;

#pragma unroll 4
        for (int d = 0; d < 128; d++) {
            float4 q4 = *(const float4*)&Qts[d * 68 + (ty << 2)];
            float4 k4 = *(const float4*)&Kts[d * 68 + (tx << 2)];
            const float qa[4] = {q4.x, q4.y, q4.z, q4.w};
            const float ka[4] = {k4.x, k4.y, k4.z, k4.w};
#pragma unroll
            for (int i = 0; i < 4; i++)
#pragma unroll
                for (int j = 0; j < 4; j++)
                    s[i][j] += qa[i] * ka[j];
        }

        const bool diag = (t == qt);
#pragma unroll
        for (int i = 0; i < 4; i++)
#pragma unroll
            for (int j = 0; j < 4; j++) {
                s[i][j] *= scale;
                if (diag && ((ty << 2) + i) < ((tx << 2) + j)) s[i][j] = -1e30f;
            }

        // online softmax per row (row owned by 16 consecutive lanes)
#pragma unroll
        for (int i = 0; i < 4; i++) {
            float mloc = fmaxf(fmaxf(s[i][0], s[i][1]), fmaxf(s[i][2], s[i][3]));
#pragma unroll
            for (int off = 8; off; off >>= 1)
                mloc = fmaxf(mloc, __shfl_xor_sync(0xffffffffu, mloc, off));
            const float mnew = fmaxf(m_run[i], mloc);
            const float alpha = __expf(m_run[i] - mnew);
            const float p0 = __expf(s[i][0] - mnew);
            const float p1 = __expf(s[i][1] - mnew);
            const float p2 = __expf(s[i][2] - mnew);
            const float p3 = __expf(s[i][3] - mnew);
            float lloc = (p0 + p1) + (p2 + p3);
#pragma unroll
            for (int off = 8; off; off >>= 1)
                lloc += __shfl_xor_sync(0xffffffffu, lloc, off);
            l_run[i] = l_run[i] * alpha + lloc;
            m_run[i] = mnew;
#pragma unroll
            for (int j = 0; j < 8; j++) oa[i][j] *= alpha;
            // store P transposed: Pts[k][r]
            const int rr = (ty << 2) + i;
            Pts[((tx << 2) + 0) * 68 + rr] = p0;
            Pts[((tx << 2) + 1) * 68 + rr] = p1;
            Pts[((tx << 2) + 2) * 68 + rr] = p2;
            Pts[((tx << 2) + 3) * 68 + rr] = p3;
        }
        __syncthreads();

        // O += P V   (4 rows x 8 cols per thread)
#pragma unroll 2
        for (int k = 0; k < 64; k++) {
            float4 p4 = *(const float4*)&Pts[k * 68 + (ty << 2)];
            const float pr[4] = {p4.x, p4.y, p4.z, p4.w};
            float4 v0 = *(const float4*)&Vs[k * 128 + (tx << 3)];
            float4 v1 = *(const float4*)&Vs[k * 128 + (tx << 3) + 4];
            const float vr[8] = {v0.x, v0.y, v0.z, v0.w, v1.x, v1.y, v1.z, v1.w};
#pragma unroll
            for (int i = 0; i < 4; i++)
#pragma unroll
                for (int j = 0; j < 8; j++)
                    oa[i][j] += pr[i] * vr[j];
        }
    }

    // normalize + write [B,S,H,HD]
#pragma unroll
    for (int i = 0; i < 4; i++) {
        const float inv = 1.0f / l_run[i];
        float* op = O + (size_t)((b << 11) + qs + (ty << 2) + i) * DD + (h << 7) + (tx << 3);
        *(float4*)op       = make_float4(oa[i][0] * inv, oa[i][1] * inv, oa[i][2] * inv, oa[i][3] * inv);
        *(float4*)(op + 4) = make_float4(oa[i][4] * inv, oa[i][5] * inv, oa[i][6] * inv, oa[i][7] * inv);
    }
}

// ---------------------------------------------------------------------------
extern "C" void kernel_launch(void* const* d_in, const int* in_sizes, int n_in,
                              void* d_out, int out_size) {
    const float* hidden = (const float*)d_in[0];
    // d_in[1] = attention_mask (pure causal; handled analytically)
    const float* cosp = (const float*)d_in[2];
    const float* sinp = (const float*)d_in[3];
    const float* Wq   = (const float*)d_in[4];
    const float* Wk   = (const float*)d_in[5];
    const float* Wv   = (const float*)d_in[6];
    const float* Wo   = (const float*)d_in[7];
    float* out = (float*)d_out;

    float *Qb, *Kb, *Vb, *Ob;
    cudaGetSymbolAddress((void**)&Qb, g_Q);
    cudaGetSymbolAddress((void**)&Kb, g_K);
    cudaGetSymbolAddress((void**)&Vb, g_V);
    cudaGetSymbolAddress((void**)&Ob, g_O);

    cudaFuncSetAttribute(flash_attn, cudaFuncAttributeMaxDynamicSharedMemorySize, FLASH_SMEM);

    dim3 blk(256);
    // QKV projections
    sgemm128<<<dim3(DD / 128, MROWS / 128), blk>>>(hidden, Wq, Qb, MROWS, DD,  DD);
    sgemm128<<<dim3(KVD / 128, MROWS / 128), blk>>>(hidden, Wk, Kb, MROWS, KVD, DD);
    sgemm128<<<dim3(KVD / 128, MROWS / 128), blk>>>(hidden, Wv, Vb, MROWS, KVD, DD);
    // RoPE on Q and K (in place)
    rope_kernel<<<dim3(MROWS, HH + KVH), 128>>>(Qb, Kb, cosp, sinp);
    // causal flash attention
    flash_attn<<<dim3(SS / 64, HH, BB), 256, FLASH_SMEM>>>(Qb, Kb, Vb, Ob);
    // output projection
    sgemm128<<<dim3(DD / 128, MROWS / 128), blk>>>(Ob, Wo, out, MROWS, DD, DD);
}

// round 9
// speedup vs baseline: 1.5600x; 1.5600x over previous
#include <cuda_runtime.h>
#include <math.h>
#include <stdint.h>

// Problem constants
#define BB   2
#define SS   2048
#define DD   2048
#define HH   16
#define KVH  4
#define HD   128
#define MROWS (BB * SS)        // 4096
#define KVD  (KVH * HD)        // 512

// Scratch buffers (device globals: allocation-free rule)
__device__ float g_Q[(size_t)MROWS * DD];   // [B,S,H,HD]
__device__ float g_K[(size_t)MROWS * KVD];  // [B,S,KVH,HD]
__device__ float g_V[(size_t)MROWS * KVD];
__device__ float g_O[(size_t)MROWS * DD];

// ---------------------------------------------------------------------------
// tf32 helpers
// ---------------------------------------------------------------------------
__device__ __forceinline__ float f2tf32(float x) {
    uint32_t u;
    asm("cvt.rna.tf32.f32 %0, %1;" : "=r"(u) : "f"(x));
    return __uint_as_float(u);
}

__device__ __forceinline__ void mma_tf32(float c[4], const uint32_t a[4], const uint32_t b[2]) {
    asm volatile(
        "mma.sync.aligned.m16n8k8.row.col.f32.tf32.tf32.f32 "
        "{%0,%1,%2,%3}, {%4,%5,%6,%7}, {%8,%9}, {%0,%1,%2,%3};"
        : "+f"(c[0]), "+f"(c[1]), "+f"(c[2]), "+f"(c[3])
        : "r"(a[0]), "r"(a[1]), "r"(a[2]), "r"(a[3]), "r"(b[0]), "r"(b[1]));
}

// ---------------------------------------------------------------------------
// tf32 tensor-core GEMM: C[M,N] = A[M,K] @ B[K,N], row-major fp32 in/out.
// BM=BN=128, BK=32, 256 threads (8 warps, 4x2), warp tile 32x64,
// per-warp 2x8 fragments of m16n8k8.
// Requires M%128==0, N%128==0, K%32==0.
// Smem: A m-major stride 36 (conflict-free frag LDS: banks 4*grp+qid),
//       B k-major stride 136 (banks 8*qid+grp). Both STS paths conflict-free.
// ---------------------------------------------------------------------------
#define LDA 36
#define LDB 136

__global__ __launch_bounds__(256) void gemm_tf32(const float* __restrict__ A,
                                                 const float* __restrict__ B,
                                                 float* __restrict__ C,
                                                 int M, int N, int K) {
    __shared__ float As[128 * LDA];  // 18.0 KB
    __shared__ float Bs[32 * LDB];   // 17.0 KB

    const int tid = threadIdx.x;
    const int bm = blockIdx.y, bn = blockIdx.x;
    const int warp = tid >> 5, lane = tid & 31;
    const int mw = warp & 3;   // 0..3 along M
    const int nw = warp >> 2;  // 0..1 along N
    const int grp = lane >> 2; // 0..7
    const int qid = lane & 3;  // 0..3

    // A global-load mapping: 4 passes of 32 rows x 32 cols (coalesced 128B/8 lanes)
    const int ar = tid >> 3;        // 0..31
    const int ac = (tid & 7) << 2;  // 0,4,...,28
    // B global-load mapping: 4 passes of 8 rows x 128 cols (coalesced 512B/warp)
    const int br = tid >> 5;        // 0..7
    const int bc = (tid & 31) << 2; // 0..124

    const float* Ag = A + (size_t)(bm * 128) * K;
    const float* Bg = B + bn * 128;

    float acc[2][8][4];
#pragma unroll
    for (int mt = 0; mt < 2; mt++)
#pragma unroll
        for (int nt = 0; nt < 8; nt++)
#pragma unroll
            for (int e = 0; e < 4; e++) acc[mt][nt][e] = 0.f;

    float4 ra[4], rb[4];
    // prefetch tile 0
#pragma unroll
    for (int p = 0; p < 4; p++) {
        ra[p] = *(const float4*)(Ag + (size_t)(p * 32 + ar) * K + ac);
        rb[p] = *(const float4*)(Bg + (size_t)(p * 8 + br) * N + bc);
    }

    for (int k0 = 0; k0 < K; k0 += 32) {
        __syncthreads();
#pragma unroll
        for (int p = 0; p < 4; p++) {
            float4 v = ra[p];
            *(float4*)&As[(p * 32 + ar) * LDA + ac] =
                make_float4(f2tf32(v.x), f2tf32(v.y), f2tf32(v.z), f2tf32(v.w));
            float4 w = rb[p];
            *(float4*)&Bs[(p * 8 + br) * LDB + bc] =
                make_float4(f2tf32(w.x), f2tf32(w.y), f2tf32(w.z), f2tf32(w.w));
        }
        __syncthreads();

        if (k0 + 32 < K) {  // prefetch next tile (overlaps with compute below)
#pragma unroll
            for (int p = 0; p < 4; p++) {
                ra[p] = *(const float4*)(Ag + (size_t)(p * 32 + ar) * K + k0 + 32 + ac);
                rb[p] = *(const float4*)(Bg + (size_t)(k0 + 32 + p * 8 + br) * N + bc);
            }
        }

#pragma unroll
        for (int kk = 0; kk < 4; kk++) {
            const int kb = kk * 8;
            uint32_t af[2][4];
#pragma unroll
            for (int mt = 0; mt < 2; mt++) {
                const int r = mw * 32 + mt * 16 + grp;
                af[mt][0] = __float_as_uint(As[(r)     * LDA + kb + qid]);
                af[mt][1] = __float_as_uint(As[(r + 8) * LDA + kb + qid]);
                af[mt][2] = __float_as_uint(As[(r)     * LDA + kb + qid + 4]);
                af[mt][3] = __float_as_uint(As[(r + 8) * LDA + kb + qid + 4]);
            }
            uint32_t bf[8][2];
#pragma unroll
            for (int nt = 0; nt < 8; nt++) {
                const int c = nw * 64 + nt * 8 + grp;
                bf[nt][0] = __float_as_uint(Bs[(kb + qid)     * LDB + c]);
                bf[nt][1] = __float_as_uint(Bs[(kb + qid + 4) * LDB + c]);
            }
#pragma unroll
            for (int mt = 0; mt < 2; mt++)
#pragma unroll
                for (int nt = 0; nt < 8; nt++)
                    mma_tf32(acc[mt][nt], af[mt], bf[nt]);
        }
    }

    // epilogue: direct float2 stores (c0,c1 contiguous; c2,c3 at row+8)
#pragma unroll
    for (int mt = 0; mt < 2; mt++) {
        const int row = bm * 128 + mw * 32 + mt * 16 + grp;
#pragma unroll
        for (int nt = 0; nt < 8; nt++) {
            const int col = bn * 128 + nw * 64 + nt * 8 + qid * 2;
            *(float2*)&C[(size_t)row * N + col]       = make_float2(acc[mt][nt][0], acc[mt][nt][1]);
            *(float2*)&C[(size_t)(row + 8) * N + col] = make_float2(acc[mt][nt][2], acc[mt][nt][3]);
        }
    }
}

// ---------------------------------------------------------------------------
// RoPE applied in-place to Q (heads 0..15) and K (heads 16..19).
// ---------------------------------------------------------------------------
__global__ __launch_bounds__(128) void rope_kernel(float* __restrict__ Q,
                                                   float* __restrict__ Kb,
                                                   const float* __restrict__ cosp,
                                                   const float* __restrict__ sinp) {
    const int bs = blockIdx.x;            // 0..4095
    const int hy = blockIdx.y;            // 0..19
    const int s  = bs & (SS - 1);

    __shared__ float x[HD];
    float* ptr;
    if (hy < HH) ptr = Q  + (size_t)bs * DD  + hy * HD;
    else         ptr = Kb + (size_t)bs * KVD + (hy - HH) * HD;

    x[threadIdx.x] = ptr[threadIdx.x];
    __syncthreads();
    if (threadIdx.x < 64) {
        const int i = threadIdx.x;
        const float c  = cosp[s * 64 + i];
        const float sn = sinp[s * 64 + i];
        const float p1 = x[2 * i], p2 = x[2 * i + 1];
        ptr[i]      = p1 * c - p2 * sn;
        ptr[i + 64] = p2 * c + p1 * sn;
    }
}

// ---------------------------------------------------------------------------
// fp32 causal flash attention with GQA (q head h -> kv head h/4). Unchanged.
// ---------------------------------------------------------------------------
#define FLASH_SMEM ((128 * 68 * 2 + 64 * 128 + 64 * 68) * 4)

__global__ __launch_bounds__(256) void flash_attn(const float* __restrict__ Q,
                                                  const float* __restrict__ Kg,
                                                  const float* __restrict__ Vg,
                                                  float* __restrict__ O) {
    extern __shared__ float sm[];
    float* Qts = sm;                 // [128][68]  (d-major, transposed)
    float* Kts = sm + 128 * 68;      // [128][68]
    float* Vs  = Kts + 128 * 68;     // [64][128]
    float* Pts = Vs + 64 * 128;      // [64][68]   (k-major)

    const int qt = blockIdx.x, h = blockIdx.y, b = blockIdx.z;
    const int kvh = h >> 2;
    const int tid = threadIdx.x;
    const int tx = tid & 15, ty = tid >> 4;
    const int qs = qt << 6;
    const float scale = 0.088388347648318447f;  // 1/sqrt(128)

    for (int idx = tid; idx < 64 * 32; idx += 256) {
        const int r = idx >> 5, d4 = (idx & 31) << 2;
        float4 v = *(const float4*)(Q + (size_t)((b << 11) + qs + r) * DD + (h << 7) + d4);
        Qts[(d4 + 0) * 68 + r] = v.x; Qts[(d4 + 1) * 68 + r] = v.y;
        Qts[(d4 + 2) * 68 + r] = v.z; Qts[(d4 + 3) * 68 + r] = v.w;
    }

    float m_run[4], l_run[4], oa[4][8];
#pragma unroll
    for (int i = 0; i < 4; i++) {
        m_run[i] = -1e30f; l_run[i] = 0.f;
#pragma unroll
        for (int j = 0; j < 8; j++) oa[i][j] = 0.f;
    }

    for (int t = 0; t <= qt; t++) {
        const int ks = t << 6;
        __syncthreads();
        for (int idx = tid; idx < 64 * 32; idx += 256) {
            const int r = idx >> 5, d4 = (idx & 31) << 2;
            const size_t gro = (size_t)((b << 11) + ks + r) * KVD + (kvh << 7) + d4;
            float4 kv = *(const float4*)(Kg + gro);
            Kts[(d4 + 0) * 68 + r] = kv.x; Kts[(d4 + 1) * 68 + r] = kv.y;
            Kts[(d4 + 2) * 68 + r] = kv.z; Kts[(d4 + 3) * 68 + r] = kv.w;
            float4 vv = *(const float4*)(Vg + gro);
            *(float4*)&Vs[r * 128 + d4] = vv;
        }
        __syncthreads();

        float s[4][4];
#pragma unroll
        for (int i = 0; i < 4; i++)
#pragma unroll
            for (int j = 0; j < 4; j++) s[i][j] = 0.f;

#pragma unroll 4
        for (int d = 0; d < 128; d++) {
            float4 q4 = *(const float4*)&Qts[d * 68 + (ty << 2)];
            float4 k4 = *(const float4*)&Kts[d * 68 + (tx << 2)];
            const float qa[4] = {q4.x, q4.y, q4.z, q4.w};
            const float ka[4] = {k4.x, k4.y, k4.z, k4.w};
#pragma unroll
            for (int i = 0; i < 4; i++)
#pragma unroll
                for (int j = 0; j < 4; j++)
                    s[i][j] += qa[i] * ka[j];
        }

        const bool diag = (t == qt);
#pragma unroll
        for (int i = 0; i < 4; i++)
#pragma unroll
            for (int j = 0; j < 4; j++) {
                s[i][j] *= scale;
                if (diag && ((ty << 2) + i) < ((tx << 2) + j)) s[i][j] = -1e30f;
            }

#pragma unroll
        for (int i = 0; i < 4; i++) {
            float mloc = fmaxf(fmaxf(s[i][0], s[i][1]), fmaxf(s[i][2], s[i][3]));
#pragma unroll
            for (int off = 8; off; off >>= 1)
                mloc = fmaxf(mloc, __shfl_xor_sync(0xffffffffu, mloc, off));
            const float mnew = fmaxf(m_run[i], mloc);
            const float alpha = __expf(m_run[i] - mnew);
            const float p0 = __expf(s[i][0] - mnew);
            const float p1 = __expf(s[i][1] - mnew);
            const float p2 = __expf(s[i][2] - mnew);
            const float p3 = __expf(s[i][3] - mnew);
            float lloc = (p0 + p1) + (p2 + p3);
#pragma unroll
            for (int off = 8; off; off >>= 1)
                lloc += __shfl_xor_sync(0xffffffffu, lloc, off);
            l_run[i] = l_run[i] * alpha + lloc;
            m_run[i] = mnew;
#pragma unroll
            for (int j = 0; j < 8; j++) oa[i][j] *= alpha;
            const int rr = (ty << 2) + i;
            Pts[((tx << 2) + 0) * 68 + rr] = p0;
            Pts[((tx << 2) + 1) * 68 + rr] = p1;
            Pts[((tx << 2) + 2) * 68 + rr] = p2;
            Pts[((tx << 2) + 3) * 68 + rr] = p3;
        }
        __syncthreads();

#pragma unroll 2
        for (int k = 0; k < 64; k++) {
            float4 p4 = *(const float4*)&Pts[k * 68 + (ty << 2)];
            const float pr[4] = {p4.x, p4.y, p4.z, p4.w};
            float4 v0 = *(const float4*)&Vs[k * 128 + (tx << 3)];
            float4 v1 = *(const float4*)&Vs[k * 128 + (tx << 3) + 4];
            const float vr[8] = {v0.x, v0.y, v0.z, v0.w, v1.x, v1.y, v1.z, v1.w};
#pragma unroll
            for (int i = 0; i < 4; i++)
#pragma unroll
                for (int j = 0; j < 8; j++)
                    oa[i][j] += pr[i] * vr[j];
        }
    }

#pragma unroll
    for (int i = 0; i < 4; i++) {
        const float inv = 1.0f / l_run[i];
        float* op = O + (size_t)((b << 11) + qs + (ty << 2) + i) * DD + (h << 7) + (tx << 3);
        *(float4*)op       = make_float4(oa[i][0] * inv, oa[i][1] * inv, oa[i][2] * inv, oa[i][3] * inv);
        *(float4*)(op + 4) = make_float4(oa[i][4] * inv, oa[i][5] * inv, oa[i][6] * inv, oa[i][7] * inv);
    }
}

// ---------------------------------------------------------------------------
extern "C" void kernel_launch(void* const* d_in, const int* in_sizes, int n_in,
                              void* d_out, int out_size) {
    const float* hidden = (const float*)d_in[0];
    // d_in[1] = attention_mask (pure causal; handled analytically)
    const float* cosp = (const float*)d_in[2];
    const float* sinp = (const float*)d_in[3];
    const float* Wq   = (const float*)d_in[4];
    const float* Wk   = (const float*)d_in[5];
    const float* Wv   = (const float*)d_in[6];
    const float* Wo   = (const float*)d_in[7];
    float* out = (float*)d_out;

    float *Qb, *Kb, *Vb, *Ob;
    cudaGetSymbolAddress((void**)&Qb, g_Q);
    cudaGetSymbolAddress((void**)&Kb, g_K);
    cudaGetSymbolAddress((void**)&Vb, g_V);
    cudaGetSymbolAddress((void**)&Ob, g_O);

    cudaFuncSetAttribute(flash_attn, cudaFuncAttributeMaxDynamicSharedMemorySize, FLASH_SMEM);

    dim3 blk(256);
    // QKV projections (tf32 tensor cores)
    gemm_tf32<<<dim3(DD / 128, MROWS / 128), blk>>>(hidden, Wq, Qb, MROWS, DD,  DD);
    gemm_tf32<<<dim3(KVD / 128, MROWS / 128), blk>>>(hidden, Wk, Kb, MROWS, KVD, DD);
    gemm_tf32<<<dim3(KVD / 128, MROWS / 128), blk>>>(hidden, Wv, Vb, MROWS, KVD, DD);
    // RoPE on Q and K (in place)
    rope_kernel<<<dim3(MROWS, HH + KVH), 128>>>(Qb, Kb, cosp, sinp);
    // causal flash attention (fp32)
    flash_attn<<<dim3(SS / 64, HH, BB), 256, FLASH_SMEM>>>(Qb, Kb, Vb, Ob);
    // output projection (tf32 tensor cores)
    gemm_tf32<<<dim3(DD / 128, MROWS / 128), blk>>>(Ob, Wo, out, MROWS, DD, DD);
}

// round 10
// speedup vs baseline: 3.0787x; 1.9735x over previous
#include <cuda_runtime.h>
#include <cuda_bf16.h>
#include <math.h>
#include <stdint.h>

// Problem constants
#define BB   2
#define SS   2048
#define DD   2048
#define HH   16
#define KVH  4
#define HD   128
#define MROWS (BB * SS)        // 4096
#define KVD  (KVH * HD)        // 512

// Scratch buffers (device globals: allocation-free rule)
__device__ float g_Q[(size_t)MROWS * DD];   // [B,S,H,HD]
__device__ float g_K[(size_t)MROWS * KVD];  // [B,S,KVH,HD]
__device__ float g_V[(size_t)MROWS * KVD];
__device__ float g_O[(size_t)MROWS * DD];

// ---------------------------------------------------------------------------
// helpers
// ---------------------------------------------------------------------------
__device__ __forceinline__ float f2tf32(float x) {
    uint32_t u;
    asm("cvt.rna.tf32.f32 %0, %1;" : "=r"(u) : "f"(x));
    return __uint_as_float(u);
}

__device__ __forceinline__ void mma_tf32(float c[4], const uint32_t a[4], const uint32_t b[2]) {
    asm volatile(
        "mma.sync.aligned.m16n8k8.row.col.f32.tf32.tf32.f32 "
        "{%0,%1,%2,%3}, {%4,%5,%6,%7}, {%8,%9}, {%0,%1,%2,%3};"
        : "+f"(c[0]), "+f"(c[1]), "+f"(c[2]), "+f"(c[3])
        : "r"(a[0]), "r"(a[1]), "r"(a[2]), "r"(a[3]), "r"(b[0]), "r"(b[1]));
}

__device__ __forceinline__ void mma_bf16(float c[4], const uint32_t a[4], const uint32_t b[2]) {
    asm volatile(
        "mma.sync.aligned.m16n8k16.row.col.f32.bf16.bf16.f32 "
        "{%0,%1,%2,%3}, {%4,%5,%6,%7}, {%8,%9}, {%0,%1,%2,%3};"
        : "+f"(c[0]), "+f"(c[1]), "+f"(c[2]), "+f"(c[3])
        : "r"(a[0]), "r"(a[1]), "r"(a[2]), "r"(a[3]), "r"(b[0]), "r"(b[1]));
}

// split (x,y) into packed bf16x2 hi and lo planes: x = hi + lo + O(2^-18 x)
__device__ __forceinline__ void split2(float x, float y, uint32_t& hi, uint32_t& lo) {
    __nv_bfloat162 h2 = __float22bfloat162_rn(make_float2(x, y));
    float2 hf = __bfloat1622float2(h2);
    __nv_bfloat162 l2 = __float22bfloat162_rn(make_float2(x - hf.x, y - hf.y));
    hi = reinterpret_cast<uint32_t&>(h2);
    lo = reinterpret_cast<uint32_t&>(l2);
}

// ---------------------------------------------------------------------------
// tf32 tensor-core GEMM (unchanged from round 9)
// ---------------------------------------------------------------------------
#define LDA 36
#define LDB 136

__global__ __launch_bounds__(256) void gemm_tf32(const float* __restrict__ A,
                                                 const float* __restrict__ B,
                                                 float* __restrict__ C,
                                                 int M, int N, int K) {
    __shared__ float As[128 * LDA];
    __shared__ float Bs[32 * LDB];

    const int tid = threadIdx.x;
    const int bm = blockIdx.y, bn = blockIdx.x;
    const int warp = tid >> 5, lane = tid & 31;
    const int mw = warp & 3;
    const int nw = warp >> 2;
    const int grp = lane >> 2;
    const int qid = lane & 3;

    const int ar = tid >> 3;
    const int ac = (tid & 7) << 2;
    const int br = tid >> 5;
    const int bc = (tid & 31) << 2;

    const float* Ag = A + (size_t)(bm * 128) * K;
    const float* Bg = B + bn * 128;

    float acc[2][8][4];
#pragma unroll
    for (int mt = 0; mt < 2; mt++)
#pragma unroll
        for (int nt = 0; nt < 8; nt++)
#pragma unroll
            for (int e = 0; e < 4; e++) acc[mt][nt][e] = 0.f;

    float4 ra[4], rb[4];
#pragma unroll
    for (int p = 0; p < 4; p++) {
        ra[p] = *(const float4*)(Ag + (size_t)(p * 32 + ar) * K + ac);
        rb[p] = *(const float4*)(Bg + (size_t)(p * 8 + br) * N + bc);
    }

    for (int k0 = 0; k0 < K; k0 += 32) {
        __syncthreads();
#pragma unroll
        for (int p = 0; p < 4; p++) {
            float4 v = ra[p];
            *(float4*)&As[(p * 32 + ar) * LDA + ac] =
                make_float4(f2tf32(v.x), f2tf32(v.y), f2tf32(v.z), f2tf32(v.w));
            float4 w = rb[p];
            *(float4*)&Bs[(p * 8 + br) * LDB + bc] =
                make_float4(f2tf32(w.x), f2tf32(w.y), f2tf32(w.z), f2tf32(w.w));
        }
        __syncthreads();

        if (k0 + 32 < K) {
#pragma unroll
            for (int p = 0; p < 4; p++) {
                ra[p] = *(const float4*)(Ag + (size_t)(p * 32 + ar) * K + k0 + 32 + ac);
                rb[p] = *(const float4*)(Bg + (size_t)(k0 + 32 + p * 8 + br) * N + bc);
            }
        }

#pragma unroll
        for (int kk = 0; kk < 4; kk++) {
            const int kb = kk * 8;
            uint32_t af[2][4];
#pragma unroll
            for (int mt = 0; mt < 2; mt++) {
                const int r = mw * 32 + mt * 16 + grp;
                af[mt][0] = __float_as_uint(As[(r)     * LDA + kb + qid]);
                af[mt][1] = __float_as_uint(As[(r + 8) * LDA + kb + qid]);
                af[mt][2] = __float_as_uint(As[(r)     * LDA + kb + qid + 4]);
                af[mt][3] = __float_as_uint(As[(r + 8) * LDA + kb + qid + 4]);
            }
            uint32_t bf[8][2];
#pragma unroll
            for (int nt = 0; nt < 8; nt++) {
                const int c = nw * 64 + nt * 8 + grp;
                bf[nt][0] = __float_as_uint(Bs[(kb + qid)     * LDB + c]);
                bf[nt][1] = __float_as_uint(Bs[(kb + qid + 4) * LDB + c]);
            }
#pragma unroll
            for (int mt = 0; mt < 2; mt++)
#pragma unroll
                for (int nt = 0; nt < 8; nt++)
                    mma_tf32(acc[mt][nt], af[mt], bf[nt]);
        }
    }

#pragma unroll
    for (int mt = 0; mt < 2; mt++) {
        const int row = bm * 128 + mw * 32 + mt * 16 + grp;
#pragma unroll
        for (int nt = 0; nt < 8; nt++) {
            const int col = bn * 128 + nw * 64 + nt * 8 + qid * 2;
            *(float2*)&C[(size_t)row * N + col]       = make_float2(acc[mt][nt][0], acc[mt][nt][1]);
            *(float2*)&C[(size_t)(row + 8) * N + col] = make_float2(acc[mt][nt][2], acc[mt][nt][3]);
        }
    }
}

// ---------------------------------------------------------------------------
// RoPE (unchanged)
// ---------------------------------------------------------------------------
__global__ __launch_bounds__(128) void rope_kernel(float* __restrict__ Q,
                                                   float* __restrict__ Kb,
                                                   const float* __restrict__ cosp,
                                                   const float* __restrict__ sinp) {
    const int bs = blockIdx.x;
    const int hy = blockIdx.y;
    const int s  = bs & (SS - 1);

    __shared__ float x[HD];
    float* ptr;
    if (hy < HH) ptr = Q  + (size_t)bs * DD  + hy * HD;
    else         ptr = Kb + (size_t)bs * KVD + (hy - HH) * HD;

    x[threadIdx.x] = ptr[threadIdx.x];
    __syncthreads();
    if (threadIdx.x < 64) {
        const int i = threadIdx.x;
        const float c  = cosp[s * 64 + i];
        const float sn = sinp[s * 64 + i];
        const float p1 = x[2 * i], p2 = x[2 * i + 1];
        ptr[i]      = p1 * c - p2 * sn;
        ptr[i + 64] = p2 * c + p1 * sn;
    }
}

// ---------------------------------------------------------------------------
// bf16x3-split tensor-core flash attention.
// Q tile 128 rows, K/V tile 64 keys, 256 threads = 8 warps.
// Warp w owns query rows 16w..16w+15 and the FULL key width (n64) -> softmax
// is warp-local and P is register-resident.
// Error: each operand split hi+lo (bf16); terms hi*hi + hi*lo + lo*hi kept
// -> per-stage relative error ~2^-18, negligible vs the tf32 projections.
// Smem: Khi/Klo packed-bf16x2 [64][68] words (stride 136 bf16),
//       Vthi/Vtlo transposed bf16 [128][72] (=[128][36] words).
// All mainloop fragment LDS patterns are bank-conflict-free.
// ---------------------------------------------------------------------------
#define FLASH_SMEM_BYTES ((2 * 64 * 68 + 2 * 128 * 36) * 4)   // 71680

__global__ __launch_bounds__(256) void flash_bf16(const float* __restrict__ Q,
                                                  const float* __restrict__ Kg,
                                                  const float* __restrict__ Vg,
                                                  float* __restrict__ O) {
    extern __shared__ uint32_t smw[];
    uint32_t* Khi  = smw;                    // [64][68] words
    uint32_t* Klo  = smw + 64 * 68;
    uint32_t* Vthi = smw + 2 * 64 * 68;      // [128][36] words  (bf16 [128][72])
    uint32_t* Vtlo = Vthi + 128 * 36;
    __nv_bfloat16* vhs = (__nv_bfloat16*)Vthi;
    __nv_bfloat16* vls = (__nv_bfloat16*)Vtlo;

    const int bq = (int)(gridDim.x - 1) - (int)blockIdx.x;  // big tiles first
    const int h = blockIdx.y, b = blockIdx.z;
    const int kvh = h >> 2;
    const int tid = threadIdx.x, w = tid >> 5, lane = tid & 31;
    const int grp = lane >> 2, qid = lane & 3;
    const int qs = bq << 7;
    const float scale = 0.088388347648318447f;  // 1/sqrt(128)

    // ---- Q fragments (pre-scaled), register-resident for the whole block ----
    uint32_t qhi[8][4], qlo[8][4];
    {
        const float* q0 = Q + (size_t)((b << 11) + qs + (w << 4) + grp) * DD + (h << 7);
        const float* q1 = q0 + (size_t)8 * DD;
#pragma unroll
        for (int kk = 0; kk < 8; kk++) {
            const int c = (kk << 4) + (qid << 1);
            float2 x0 = *(const float2*)(q0 + c);
            float2 x1 = *(const float2*)(q1 + c);
            float2 x2 = *(const float2*)(q0 + c + 8);
            float2 x3 = *(const float2*)(q1 + c + 8);
            split2(x0.x * scale, x0.y * scale, qhi[kk][0], qlo[kk][0]);
            split2(x1.x * scale, x1.y * scale, qhi[kk][1], qlo[kk][1]);
            split2(x2.x * scale, x2.y * scale, qhi[kk][2], qlo[kk][2]);
            split2(x3.x * scale, x3.y * scale, qhi[kk][3], qlo[kk][3]);
        }
    }

    float oacc[16][4];
#pragma unroll
    for (int f = 0; f < 16; f++)
#pragma unroll
        for (int e = 0; e < 4; e++) oacc[f][e] = 0.f;
    float m0 = -1e30f, m1 = -1e30f, l0 = 0.f, l1 = 0.f;

    const int ntiles = (bq << 1) + 2;
    for (int t = 0; t < ntiles; t++) {
        const int ks = t << 6;
        __syncthreads();  // previous tile's consumers done

        // stage K: packed bf16x2 hi/lo planes, [key][d] (d-pairs packed)
        for (int idx = tid; idx < 64 * 32; idx += 256) {
            const int key = idx >> 5, mm = idx & 31;
            float4 kv = *(const float4*)(Kg + (size_t)((b << 11) + ks + key) * KVD + (kvh << 7) + (mm << 2));
            uint32_t h0, w0, h1, w1;
            split2(kv.x, kv.y, h0, w0);
            split2(kv.z, kv.w, h1, w1);
            Khi[key * 68 + 2 * mm]     = h0;
            Khi[key * 68 + 2 * mm + 1] = h1;
            Klo[key * 68 + 2 * mm]     = w0;
            Klo[key * 68 + 2 * mm + 1] = w1;
        }
        // stage V transposed: bf16 scalars at [d][key]
        for (int idx = tid; idx < 64 * 32; idx += 256) {
            const int key = idx & 63, dm = idx >> 6;  // dm 0..31
            const int d4 = dm << 2;
            float4 vv = *(const float4*)(Vg + (size_t)((b << 11) + ks + key) * KVD + (kvh << 7) + d4);
            float vals[4] = {vv.x, vv.y, vv.z, vv.w};
#pragma unroll
            for (int j = 0; j < 4; j++) {
                __nv_bfloat16 hb = __float2bfloat16_rn(vals[j]);
                float r = vals[j] - __bfloat162float(hb);
                vhs[(d4 + j) * 72 + key] = hb;
                vls[(d4 + j) * 72 + key] = __float2bfloat16_rn(r);
            }
        }
        __syncthreads();

        // ---- S = Q K^T (3-term bf16 split) ----
        float sacc[8][4];
#pragma unroll
        for (int nf = 0; nf < 8; nf++)
#pragma unroll
            for (int e = 0; e < 4; e++) sacc[nf][e] = 0.f;

#pragma unroll
        for (int kk = 0; kk < 8; kk++) {
#pragma unroll
            for (int nf = 0; nf < 8; nf++) {
                const int base = (nf * 8 + grp) * 68 + kk * 8 + qid;
                uint32_t bh[2] = {Khi[base], Khi[base + 4]};
                uint32_t bl[2] = {Klo[base], Klo[base + 4]};
                mma_bf16(sacc[nf], qhi[kk], bh);
                mma_bf16(sacc[nf], qhi[kk], bl);
                mma_bf16(sacc[nf], qlo[kk], bh);
            }
        }

        // ---- causal mask on the two partial tiles ----
        if (t >= (bq << 1)) {
            const int g0 = qs + (w << 4) + grp, g1 = g0 + 8;
#pragma unroll
            for (int nf = 0; nf < 8; nf++) {
                const int k0 = ks + nf * 8 + (qid << 1);
                if (k0     > g0) sacc[nf][0] = -1e30f;
                if (k0 + 1 > g0) sacc[nf][1] = -1e30f;
                if (k0     > g1) sacc[nf][2] = -1e30f;
                if (k0 + 1 > g1) sacc[nf][3] = -1e30f;
            }
        }

        // ---- warp-local online softmax (rows grp and grp+8) ----
        float mx0 = -1e30f, mx1 = -1e30f;
#pragma unroll
        for (int nf = 0; nf < 8; nf++) {
            mx0 = fmaxf(mx0, fmaxf(sacc[nf][0], sacc[nf][1]));
            mx1 = fmaxf(mx1, fmaxf(sacc[nf][2], sacc[nf][3]));
        }
        mx0 = fmaxf(mx0, __shfl_xor_sync(0xffffffffu, mx0, 1));
        mx0 = fmaxf(mx0, __shfl_xor_sync(0xffffffffu, mx0, 2));
        mx1 = fmaxf(mx1, __shfl_xor_sync(0xffffffffu, mx1, 1));
        mx1 = fmaxf(mx1, __shfl_xor_sync(0xffffffffu, mx1, 2));
        const float mn0 = fmaxf(m0, mx0), mn1 = fmaxf(m1, mx1);
        const float a0 = __expf(m0 - mn0), a1 = __expf(m1 - mn1);
        float s0 = 0.f, s1 = 0.f;
#pragma unroll
        for (int nf = 0; nf < 8; nf++) {
            sacc[nf][0] = __expf(sacc[nf][0] - mn0);
            sacc[nf][1] = __expf(sacc[nf][1] - mn0);
            sacc[nf][2] = __expf(sacc[nf][2] - mn1);
            sacc[nf][3] = __expf(sacc[nf][3] - mn1);
            s0 += sacc[nf][0] + sacc[nf][1];
            s1 += sacc[nf][2] + sacc[nf][3];
        }
        s0 += __shfl_xor_sync(0xffffffffu, s0, 1);
        s0 += __shfl_xor_sync(0xffffffffu, s0, 2);
        s1 += __shfl_xor_sync(0xffffffffu, s1, 1);
        s1 += __shfl_xor_sync(0xffffffffu, s1, 2);
        l0 = l0 * a0 + s0;
        l1 = l1 * a1 + s1;
        m0 = mn0; m1 = mn1;
#pragma unroll
        for (int f = 0; f < 16; f++) {
            oacc[f][0] *= a0; oacc[f][1] *= a0;
            oacc[f][2] *= a1; oacc[f][3] *= a1;
        }

        // ---- pack P into bf16 hi/lo A-fragments (register-resident) ----
        uint32_t pah[8], pal[8], pbh[8], pbl[8];
#pragma unroll
        for (int nf = 0; nf < 8; nf++) {
            split2(sacc[nf][0], sacc[nf][1], pah[nf], pal[nf]);
            split2(sacc[nf][2], sacc[nf][3], pbh[nf], pbl[nf]);
        }

        // ---- O += P V (3-term bf16 split) ----
#pragma unroll
        for (int kk = 0; kk < 4; kk++) {
            uint32_t ah[4] = {pah[2 * kk], pbh[2 * kk], pah[2 * kk + 1], pbh[2 * kk + 1]};
            uint32_t al[4] = {pal[2 * kk], pbl[2 * kk], pal[2 * kk + 1], pbl[2 * kk + 1]};
#pragma unroll
            for (int nf = 0; nf < 16; nf++) {
                const int base = (nf * 8 + grp) * 36 + kk * 8 + qid;
                uint32_t bh[2] = {Vthi[base], Vthi[base + 4]};
                uint32_t bl[2] = {Vtlo[base], Vtlo[base + 4]};
                mma_bf16(oacc[nf], ah, bh);
                mma_bf16(oacc[nf], ah, bl);
                mma_bf16(oacc[nf], al, bh);
            }
        }
    }

    // ---- normalize + write O [B,S,H,HD] ----
    const float i0 = 1.0f / l0, i1 = 1.0f / l1;
    float* o0 = O + (size_t)((b << 11) + qs + (w << 4) + grp) * DD + (h << 7);
    float* o1 = o0 + (size_t)8 * DD;
#pragma unroll
    for (int nf = 0; nf < 16; nf++) {
        const int col = nf * 8 + (qid << 1);
        *(float2*)(o0 + col) = make_float2(oacc[nf][0] * i0, oacc[nf][1] * i0);
        *(float2*)(o1 + col) = make_float2(oacc[nf][2] * i1, oacc[nf][3] * i1);
    }
}

// ---------------------------------------------------------------------------
extern "C" void kernel_launch(void* const* d_in, const int* in_sizes, int n_in,
                              void* d_out, int out_size) {
    const float* hidden = (const float*)d_in[0];
    // d_in[1] = attention_mask (pure causal; handled analytically)
    const float* cosp = (const float*)d_in[2];
    const float* sinp = (const float*)d_in[3];
    const float* Wq   = (const float*)d_in[4];
    const float* Wk   = (const float*)d_in[5];
    const float* Wv   = (const float*)d_in[6];
    const float* Wo   = (const float*)d_in[7];
    float* out = (float*)d_out;

    float *Qb, *Kb, *Vb, *Ob;
    cudaGetSymbolAddress((void**)&Qb, g_Q);
    cudaGetSymbolAddress((void**)&Kb, g_K);
    cudaGetSymbolAddress((void**)&Vb, g_V);
    cudaGetSymbolAddress((void**)&Ob, g_O);

    cudaFuncSetAttribute(flash_bf16, cudaFuncAttributeMaxDynamicSharedMemorySize, FLASH_SMEM_BYTES);

    dim3 blk(256);
    // QKV projections (tf32 tensor cores)
    gemm_tf32<<<dim3(DD / 128, MROWS / 128), blk>>>(hidden, Wq, Qb, MROWS, DD,  DD);
    gemm_tf32<<<dim3(KVD / 128, MROWS / 128), blk>>>(hidden, Wk, Kb, MROWS, KVD, DD);
    gemm_tf32<<<dim3(KVD / 128, MROWS / 128), blk>>>(hidden, Wv, Vb, MROWS, KVD, DD);
    // RoPE on Q and K (in place)
    rope_kernel<<<dim3(MROWS, HH + KVH), 128>>>(Qb, Kb, cosp, sinp);
    // causal flash attention (bf16x3-split tensor cores)
    flash_bf16<<<dim3(SS / 128, HH, BB), 256, FLASH_SMEM_BYTES>>>(Qb, Kb, Vb, Ob);
    // output projection (tf32 tensor cores)
    gemm_tf32<<<dim3(DD / 128, MROWS / 128), blk>>>(Ob, Wo, out, MROWS, DD, DD);
}

// round 13
// speedup vs baseline: 3.2919x; 1.0693x over previous
#include <cuda_runtime.h>
#include <cuda_bf16.h>
#include <math.h>
#include <stdint.h>

// Problem constants
#define BB   2
#define SS   2048
#define DD   2048
#define HH   16
#define KVH  4
#define HD   128
#define MROWS (BB * SS)        // 4096
#define KVD  (KVH * HD)        // 512
#define GK   2048              // K of every projection GEMM
#define QKVD 3072              // fused QKV row width (2048 Q + 512 K + 512 V)
#define KOFF 2048
#define VOFF 2560

// Scratch buffers (device globals: allocation-free rule)
__device__ float g_QKV[(size_t)MROWS * QKVD]; // fused [B*S][Q|K|V]
__device__ float g_O[(size_t)MROWS * DD];     // attention output
__device__ float g_Af[(size_t)MROWS * GK];    // tf32-rounded A
__device__ float g_Bt[(size_t)QKVD * GK];     // tf32-rounded W^T [N][K]

// ---------------------------------------------------------------------------
// helpers
// ---------------------------------------------------------------------------
__device__ __forceinline__ uint32_t s2u32(const void* p) {
    uint32_t a;
    asm("{ .reg .u64 t; cvta.to.shared.u64 t, %1; cvt.u32.u64 %0, t; }"
        : "=r"(a) : "l"(p));
    return a;
}

__device__ __forceinline__ float f2tf32(float x) {
    uint32_t u;
    asm("cvt.rna.tf32.f32 %0, %1;" : "=r"(u) : "f"(x));
    return __uint_as_float(u);
}

__device__ __forceinline__ void mma_tf32(float c[4], const uint32_t a[4], const uint32_t b[2]) {
    asm volatile(
        "mma.sync.aligned.m16n8k8.row.col.f32.tf32.tf32.f32 "
        "{%0,%1,%2,%3}, {%4,%5,%6,%7}, {%8,%9}, {%0,%1,%2,%3};"
        : "+f"(c[0]), "+f"(c[1]), "+f"(c[2]), "+f"(c[3])
        : "r"(a[0]), "r"(a[1]), "r"(a[2]), "r"(a[3]), "r"(b[0]), "r"(b[1]));
}

__device__ __forceinline__ void mma_bf16(float c[4], const uint32_t a[4], const uint32_t b[2]) {
    asm volatile(
        "mma.sync.aligned.m16n8k16.row.col.f32.bf16.bf16.f32 "
        "{%0,%1,%2,%3}, {%4,%5,%6,%7}, {%8,%9}, {%0,%1,%2,%3};"
        : "+f"(c[0]), "+f"(c[1]), "+f"(c[2]), "+f"(c[3])
        : "r"(a[0]), "r"(a[1]), "r"(a[2]), "r"(a[3]), "r"(b[0]), "r"(b[1]));
}

// split (x,y) into packed bf16x2 hi and lo planes: x = hi + lo + O(2^-18 x)
__device__ __forceinline__ void split2(float x, float y, uint32_t& hi, uint32_t& lo) {
    __nv_bfloat162 h2 = __float22bfloat162_rn(make_float2(x, y));
    float2 hf = __bfloat1622float2(h2);
    __nv_bfloat162 l2 = __float22bfloat162_rn(make_float2(x - hf.x, y - hf.y));
    hi = reinterpret_cast<uint32_t&>(h2);
    lo = reinterpret_cast<uint32_t&>(l2);
}

#define CP_ASYNC16(dst, src) \
    asm volatile("cp.async.cg.shared.global [%0], [%1], 16;" :: "r"(dst), "l"(src))
#define CP_COMMIT() asm volatile("cp.async.commit_group;")
#define CP_WAIT1()  asm volatile("cp.async.wait_group 1;")

// ---------------------------------------------------------------------------
// convA: fp32 [M][K] -> tf32-rounded fp32 (elementwise, vectorized)
// ---------------------------------------------------------------------------
__global__ __launch_bounds__(256) void convA(const float* __restrict__ X,
                                             float* __restrict__ Y) {
    const int i = blockIdx.x * 256 + threadIdx.x;  // per float4
    float4 v = ((const float4*)X)[i];
    ((float4*)Y)[i] = make_float4(f2tf32(v.x), f2tf32(v.y), f2tf32(v.z), f2tf32(v.w));
}

// ---------------------------------------------------------------------------
// convW: fp32 W [GK][N] -> tf32-rounded transposed [N][GK] at row offset `off`.
// 32x32 smem tile transpose, block 256.
// ---------------------------------------------------------------------------
__global__ __launch_bounds__(256) void convW(const float* __restrict__ W,
                                             float* __restrict__ Out,
                                             int N, int off) {
    __shared__ float ts[32][33];
    const int tid = threadIdx.x;
    const int k0 = blockIdx.y * 32, n0 = blockIdx.x * 32;
    const int r = tid >> 5, c = tid & 31;
#pragma unroll
    for (int j = 0; j < 4; j++)
        ts[j * 8 + r][c] = W[(size_t)(k0 + j * 8 + r) * N + n0 + c];
    __syncthreads();
#pragma unroll
    for (int j = 0; j < 4; j++) {
        const int n = j * 8 + r;
        Out[(size_t)(off + n0 + n) * GK + k0 + c] = f2tf32(ts[c][n]);
    }
}

// ---------------------------------------------------------------------------
// tf32 tensor-core GEMM v2: C[M,N] = A[M,K] @ B^T  (B given as [N][K]).
// A, B already tf32-rounded. BM=BN=128, BK=32, 256 threads (8 warps 4x2),
// warp tile 32x64, 2x8 m16n8k8 fragments. 3-stage cp.async pipeline.
// Smem per stage: A[128][36] + B[128][36] floats (36KB); 3 stages = 108KB.
// Fragment LDS banks: 4*grp + qid (+kb)  -> conflict-free.
// ---------------------------------------------------------------------------
#define GLDA 36
#define STAGE_BYTES (2 * 128 * GLDA * 4)     // 36864
#define GEMM_SMEM   (3 * STAGE_BYTES)        // 110592

__global__ __launch_bounds__(256) void gemm_v2(const float* __restrict__ A,
                                               const float* __restrict__ B,
                                               float* __restrict__ C,
                                               int Ntot) {
    extern __shared__ char smem[];
    const uint32_t sb = s2u32(smem);
    const int tid = threadIdx.x;
    const int bn = blockIdx.x, bm = blockIdx.y;
    const int warp = tid >> 5, lane = tid & 31;
    const int mw = warp & 3, nw = warp >> 2;
    const int grp = lane >> 2, qid = lane & 3;

    // cp.async mapping: 4 chunks A + 4 chunks B per thread per stage
    const int crow = tid >> 3;          // 0..31 (row within a 32-row pass)
    const int ccol = (tid & 7) << 4;    // byte 0..112

    const char* Ag = (const char*)(A + (size_t)(bm * 128) * GK);
    const char* Bg = (const char*)(B + (size_t)(bn * 128) * GK);

    const int T = GK / 32;  // 64 K-tiles

    // issue stage s loads (tile index s + base k)
    auto load_stage = [&](int t, int stg) {
        const uint32_t base = sb + stg * STAGE_BYTES;
        const size_t kByte = (size_t)t * 128;
#pragma unroll
        for (int p = 0; p < 4; p++) {
            const int row = p * 32 + crow;
            const uint32_t d = base + row * 144 + ccol;
            CP_ASYNC16(d, Ag + (size_t)row * (GK * 4) + kByte + ccol);
            CP_ASYNC16(d + STAGE_BYTES / 2, Bg + (size_t)row * (GK * 4) + kByte + ccol);
        }
    };

    float acc[2][8][4];
#pragma unroll
    for (int mt = 0; mt < 2; mt++)
#pragma unroll
        for (int nt = 0; nt < 8; nt++)
#pragma unroll
            for (int e = 0; e < 4; e++) acc[mt][nt][e] = 0.f;

    load_stage(0, 0); CP_COMMIT();
    load_stage(1, 1); CP_COMMIT();

    for (int t = 0; t < T; t++) {
        const int stg = t % 3;
        CP_WAIT1();
        __syncthreads();

        if (t + 2 < T) load_stage(t + 2, (t + 2) % 3);
        CP_COMMIT();

        const float* As = (const float*)(smem + stg * STAGE_BYTES);
        const float* Bs = As + 128 * GLDA;

#pragma unroll
        for (int kk = 0; kk < 4; kk++) {
            const int kb = kk * 8;
            uint32_t af[2][4];
#pragma unroll
            for (int mt = 0; mt < 2; mt++) {
                const int r = mw * 32 + mt * 16 + grp;
                af[mt][0] = __float_as_uint(As[(r)     * GLDA + kb + qid]);
                af[mt][1] = __float_as_uint(As[(r + 8) * GLDA + kb + qid]);
                af[mt][2] = __float_as_uint(As[(r)     * GLDA + kb + qid + 4]);
                af[mt][3] = __float_as_uint(As[(r + 8) * GLDA + kb + qid + 4]);
            }
            uint32_t bf[8][2];
#pragma unroll
            for (int nt = 0; nt < 8; nt++) {
                const int n = nw * 64 + nt * 8 + grp;
                bf[nt][0] = __float_as_uint(Bs[n * GLDA + kb + qid]);
                bf[nt][1] = __float_as_uint(Bs[n * GLDA + kb + qid + 4]);
            }
#pragma unroll
            for (int mt = 0; mt < 2; mt++)
#pragma unroll
                for (int nt = 0; nt < 8; nt++)
                    mma_tf32(acc[mt][nt], af[mt], bf[nt]);
        }
        __syncthreads();
    }

    // epilogue: direct float2 stores
#pragma unroll
    for (int mt = 0; mt < 2; mt++) {
        const int row = bm * 128 + mw * 32 + mt * 16 + grp;
#pragma unroll
        for (int nt = 0; nt < 8; nt++) {
            const int col = bn * 128 + nw * 64 + nt * 8 + qid * 2;
            *(float2*)&C[(size_t)row * Ntot + col]       = make_float2(acc[mt][nt][0], acc[mt][nt][1]);
            *(float2*)&C[(size_t)(row + 8) * Ntot + col] = make_float2(acc[mt][nt][2], acc[mt][nt][3]);
        }
    }
}

// ---------------------------------------------------------------------------
// RoPE applied in-place to Q (heads 0..15) and K (heads 16..19) in fused QKV.
// ---------------------------------------------------------------------------
__global__ __launch_bounds__(128) void rope_kernel(float* __restrict__ QKV,
                                                   const float* __restrict__ cosp,
                                                   const float* __restrict__ sinp) {
    const int bs = blockIdx.x;
    const int hy = blockIdx.y;
    const int s  = bs & (SS - 1);

    __shared__ float x[HD];
    float* ptr;
    if (hy < HH) ptr = QKV + (size_t)bs * QKVD + hy * HD;
    else         ptr = QKV + (size_t)bs * QKVD + KOFF + (hy - HH) * HD;

    x[threadIdx.x] = ptr[threadIdx.x];
    __syncthreads();
    if (threadIdx.x < 64) {
        const int i = threadIdx.x;
        const float c  = cosp[s * 64 + i];
        const float sn = sinp[s * 64 + i];
        const float p1 = x[2 * i], p2 = x[2 * i + 1];
        ptr[i]      = p1 * c - p2 * sn;
        ptr[i + 64] = p2 * c + p1 * sn;
    }
}

// ---------------------------------------------------------------------------
// bf16x3-split tensor-core flash attention (R10, reading fused QKV buffer).
// ---------------------------------------------------------------------------
#define FLASH_SMEM_BYTES ((2 * 64 * 68 + 2 * 128 * 36) * 4)   // 71680

__global__ __launch_bounds__(256) void flash_bf16(const float* __restrict__ QKV,
                                                  float* __restrict__ O) {
    extern __shared__ uint32_t smw[];
    uint32_t* Khi  = smw;                    // [64][68] words
    uint32_t* Klo  = smw + 64 * 68;
    uint32_t* Vthi = smw + 2 * 64 * 68;      // [128][36] words  (bf16 [128][72])
    uint32_t* Vtlo = Vthi + 128 * 36;
    __nv_bfloat16* vhs = (__nv_bfloat16*)Vthi;
    __nv_bfloat16* vls = (__nv_bfloat16*)Vtlo;

    const int bq = (int)(gridDim.x - 1) - (int)blockIdx.x;  // big tiles first
    const int h = blockIdx.y, b = blockIdx.z;
    const int kvh = h >> 2;
    const int tid = threadIdx.x, w = tid >> 5, lane = tid & 31;
    const int grp = lane >> 2, qid = lane & 3;
    const int qs = bq << 7;
    const float scale = 0.088388347648318447f;  // 1/sqrt(128)

    uint32_t qhi[8][4], qlo[8][4];
    {
        const float* q0 = QKV + (size_t)((b << 11) + qs + (w << 4) + grp) * QKVD + (h << 7);
        const float* q1 = q0 + (size_t)8 * QKVD;
#pragma unroll
        for (int kk = 0; kk < 8; kk++) {
            const int c = (kk << 4) + (qid << 1);
            float2 x0 = *(const float2*)(q0 + c);
            float2 x1 = *(const float2*)(q1 + c);
            float2 x2 = *(const float2*)(q0 + c + 8);
            float2 x3 = *(const float2*)(q1 + c + 8);
            split2(x0.x * scale, x0.y * scale, qhi[kk][0], qlo[kk][0]);
            split2(x1.x * scale, x1.y * scale, qhi[kk][1], qlo[kk][1]);
            split2(x2.x * scale, x2.y * scale, qhi[kk][2], qlo[kk][2]);
            split2(x3.x * scale, x3.y * scale, qhi[kk][3], qlo[kk][3]);
        }
    }

    float oacc[16][4];
#pragma unroll
    for (int f = 0; f < 16; f++)
#pragma unroll
        for (int e = 0; e < 4; e++) oacc[f][e] = 0.f;
    float m0 = -1e30f, m1 = -1e30f, l0 = 0.f, l1 = 0.f;

    const int ntiles = (bq << 1) + 2;
    for (int t = 0; t < ntiles; t++) {
        const int ks = t << 6;
        __syncthreads();

        for (int idx = tid; idx < 64 * 32; idx += 256) {
            const int key = idx >> 5, mm = idx & 31;
            float4 kv = *(const float4*)(QKV + (size_t)((b << 11) + ks + key) * QKVD + KOFF + (kvh << 7) + (mm << 2));
            uint32_t h0, w0, h1, w1;
            split2(kv.x, kv.y, h0, w0);
            split2(kv.z, kv.w, h1, w1);
            Khi[key * 68 + 2 * mm]     = h0;
            Khi[key * 68 + 2 * mm + 1] = h1;
            Klo[key * 68 + 2 * mm]     = w0;
            Klo[key * 68 + 2 * mm + 1] = w1;
        }
        for (int idx = tid; idx < 64 * 32; idx += 256) {
            const int key = idx & 63, dm = idx >> 6;
            const int d4 = dm << 2;
            float4 vv = *(const float4*)(QKV + (size_t)((b << 11) + ks + key) * QKVD + VOFF + (kvh << 7) + d4);
            float vals[4] = {vv.x, vv.y, vv.z, vv.w};
#pragma unroll
            for (int j = 0; j < 4; j++) {
                __nv_bfloat16 hb = __float2bfloat16_rn(vals[j]);
                float r = vals[j] - __bfloat162float(hb);
                vhs[(d4 + j) * 72 + key] = hb;
                vls[(d4 + j) * 72 + key] = __float2bfloat16_rn(r);
            }
        }
        __syncthreads();

        float sacc[8][4];
#pragma unroll
        for (int nf = 0; nf < 8; nf++)
#pragma unroll
            for (int e = 0; e < 4; e++) sacc[nf][e] = 0.f;

#pragma unroll
        for (int kk = 0; kk < 8; kk++) {
#pragma unroll
            for (int nf = 0; nf < 8; nf++) {
                const int base = (nf * 8 + grp) * 68 + kk * 8 + qid;
                uint32_t bh[2] = {Khi[base], Khi[base + 4]};
                uint32_t bl[2] = {Klo[base], Klo[base + 4]};
                mma_bf16(sacc[nf], qhi[kk], bh);
                mma_bf16(sacc[nf], qhi[kk], bl);
                mma_bf16(sacc[nf], qlo[kk], bh);
            }
        }

        if (t >= (bq << 1)) {
            const int g0 = qs + (w << 4) + grp, g1 = g0 + 8;
#pragma unroll
            for (int nf = 0; nf < 8; nf++) {
                const int k0 = ks + nf * 8 + (qid << 1);
                if (k0     > g0) sacc[nf][0] = -1e30f;
                if (k0 + 1 > g0) sacc[nf][1] = -1e30f;
                if (k0     > g1) sacc[nf][2] = -1e30f;
                if (k0 + 1 > g1) sacc[nf][3] = -1e30f;
            }
        }

        float mx0 = -1e30f, mx1 = -1e30f;
#pragma unroll
        for (int nf = 0; nf < 8; nf++) {
            mx0 = fmaxf(mx0, fmaxf(sacc[nf][0], sacc[nf][1]));
            mx1 = fmaxf(mx1, fmaxf(sacc[nf][2], sacc[nf][3]));
        }
        mx0 = fmaxf(mx0, __shfl_xor_sync(0xffffffffu, mx0, 1));
        mx0 = fmaxf(mx0, __shfl_xor_sync(0xffffffffu, mx0, 2));
        mx1 = fmaxf(mx1, __shfl_xor_sync(0xffffffffu, mx1, 1));
        mx1 = fmaxf(mx1, __shfl_xor_sync(0xffffffffu, mx1, 2));
        const float mn0 = fmaxf(m0, mx0), mn1 = fmaxf(m1, mx1);
        const float a0 = __expf(m0 - mn0), a1 = __expf(m1 - mn1);
        float s0 = 0.f, s1 = 0.f;
#pragma unroll
        for (int nf = 0; nf < 8; nf++) {
            sacc[nf][0] = __expf(sacc[nf][0] - mn0);
            sacc[nf][1] = __expf(sacc[nf][1] - mn0);
            sacc[nf][2] = __expf(sacc[nf][2] - mn1);
            sacc[nf][3] = __expf(sacc[nf][3] - mn1);
            s0 += sacc[nf][0] + sacc[nf][1];
            s1 += sacc[nf][2] + sacc[nf][3];
        }
        s0 += __shfl_xor_sync(0xffffffffu, s0, 1);
        s0 += __shfl_xor_sync(0xffffffffu, s0, 2);
        s1 += __shfl_xor_sync(0xffffffffu, s1, 1);
        s1 += __shfl_xor_sync(0xffffffffu, s1, 2);
        l0 = l0 * a0 + s0;
        l1 = l1 * a1 + s1;
        m0 = mn0; m1 = mn1;
#pragma unroll
        for (int f = 0; f < 16; f++) {
            oacc[f][0] *= a0; oacc[f][1] *= a0;
            oacc[f][2] *= a1; oacc[f][3] *= a1;
        }

        uint32_t pah[8], pal[8], pbh[8], pbl[8];
#pragma unroll
        for (int nf = 0; nf < 8; nf++) {
            split2(sacc[nf][0], sacc[nf][1], pah[nf], pal[nf]);
            split2(sacc[nf][2], sacc[nf][3], pbh[nf], pbl[nf]);
        }

#pragma unroll
        for (int kk = 0; kk < 4; kk++) {
            uint32_t ah[4] = {pah[2 * kk], pbh[2 * kk], pah[2 * kk + 1], pbh[2 * kk + 1]};
            uint32_t al[4] = {pal[2 * kk], pbl[2 * kk], pal[2 * kk + 1], pbl[2 * kk + 1]};
#pragma unroll
            for (int nf = 0; nf < 16; nf++) {
                const int base = (nf * 8 + grp) * 36 + kk * 8 + qid;
                uint32_t bh[2] = {Vthi[base], Vthi[base + 4]};
                uint32_t bl[2] = {Vtlo[base], Vtlo[base + 4]};
                mma_bf16(oacc[nf], ah, bh);
                mma_bf16(oacc[nf], ah, bl);
                mma_bf16(oacc[nf], al, bh);
            }
        }
    }

    const float i0 = 1.0f / l0, i1 = 1.0f / l1;
    float* o0 = O + (size_t)((b << 11) + qs + (w << 4) + grp) * DD + (h << 7);
    float* o1 = o0 + (size_t)8 * DD;
#pragma unroll
    for (int nf = 0; nf < 16; nf++) {
        const int col = nf * 8 + (qid << 1);
        *(float2*)(o0 + col) = make_float2(oacc[nf][0] * i0, oacc[nf][1] * i0);
        *(float2*)(o1 + col) = make_float2(oacc[nf][2] * i1, oacc[nf][3] * i1);
    }
}

// ---------------------------------------------------------------------------
extern "C" void kernel_launch(void* const* d_in, const int* in_sizes, int n_in,
                              void* d_out, int out_size) {
    const float* hidden = (const float*)d_in[0];
    // d_in[1] = attention_mask (pure causal; handled analytically)
    const float* cosp = (const float*)d_in[2];
    const float* sinp = (const float*)d_in[3];
    const float* Wq   = (const float*)d_in[4];
    const float* Wk   = (const float*)d_in[5];
    const float* Wv   = (const float*)d_in[6];
    const float* Wo   = (const float*)d_in[7];
    float* out = (float*)d_out;

    float *QKVb, *Ob, *Af, *Bt;
    cudaGetSymbolAddress((void**)&QKVb, g_QKV);
    cudaGetSymbolAddress((void**)&Ob, g_O);
    cudaGetSymbolAddress((void**)&Af, g_Af);
    cudaGetSymbolAddress((void**)&Bt, g_Bt);

    cudaFuncSetAttribute(flash_bf16, cudaFuncAttributeMaxDynamicSharedMemorySize, FLASH_SMEM_BYTES);
    cudaFuncSetAttribute(gemm_v2, cudaFuncAttributeMaxDynamicSharedMemorySize, GEMM_SMEM);

    const int convA_blocks = (MROWS * GK) / 4 / 256;  // 8192

    // ---- fused QKV projection ----
    convA<<<convA_blocks, 256>>>(hidden, Af);
    convW<<<dim3(DD / 32,  GK / 32), 256>>>(Wq, Bt, DD,  0);
    convW<<<dim3(KVD / 32, GK / 32), 256>>>(Wk, Bt, KVD, KOFF);
    convW<<<dim3(KVD / 32, GK / 32), 256>>>(Wv, Bt, KVD, VOFF);
    gemm_v2<<<dim3(QKVD / 128, MROWS / 128), 256, GEMM_SMEM>>>(Af, Bt, QKVb, QKVD);
    // ---- RoPE on Q and K (in place) ----
    rope_kernel<<<dim3(MROWS, HH + KVH), 128>>>(QKVb, cosp, sinp);
    // ---- causal flash attention (bf16x3-split tensor cores) ----
    flash_bf16<<<dim3(SS / 128, HH, BB), 256, FLASH_SMEM_BYTES>>>(QKVb, Ob);
    // ---- output projection ----
    convA<<<convA_blocks, 256>>>(Ob, Af);
    convW<<<dim3(DD / 32, GK / 32), 256>>>(Wo, Bt, DD, 0);
    gemm_v2<<<dim3(DD / 128, MROWS / 128), 256, GEMM_SMEM>>>(Af, Bt, out, DD);
}

// round 14
// speedup vs baseline: 3.3021x; 1.0031x over previous
#include <cuda_runtime.h>
#include <cuda_bf16.h>
#include <math.h>
#include <stdint.h>

// Problem constants
#define BB   2
#define SS   2048
#define DD   2048
#define HH   16
#define KVH  4
#define HD   128
#define MROWS (BB * SS)        // 4096
#define KVD  (KVH * HD)        // 512
#define GK   2048              // K of every projection GEMM
#define QKVD 3072              // fused QKV row width (2048 Q + 512 K + 512 V)
#define KOFF 2048
#define VOFF 2560

// Scratch buffers (device globals: allocation-free rule)
__device__ float g_QKV[(size_t)MROWS * QKVD]; // fused [B*S][Q|K|V]
__device__ float g_O[(size_t)MROWS * DD];     // attention output
__device__ float g_Af[(size_t)MROWS * GK];    // tf32-rounded A
__device__ float g_Bt[(size_t)QKVD * GK];     // tf32-rounded W^T [N][K]

// ---------------------------------------------------------------------------
// helpers
// ---------------------------------------------------------------------------
__device__ __forceinline__ uint32_t s2u32(const void* p) {
    uint32_t a;
    asm("{ .reg .u64 t; cvta.to.shared.u64 t, %1; cvt.u32.u64 %0, t; }"
        : "=r"(a) : "l"(p));
    return a;
}

__device__ __forceinline__ float f2tf32(float x) {
    uint32_t u;
    asm("cvt.rna.tf32.f32 %0, %1;" : "=r"(u) : "f"(x));
    return __uint_as_float(u);
}

__device__ __forceinline__ void mma_tf32(float c[4], const uint32_t a[4], const uint32_t b[2]) {
    asm volatile(
        "mma.sync.aligned.m16n8k8.row.col.f32.tf32.tf32.f32 "
        "{%0,%1,%2,%3}, {%4,%5,%6,%7}, {%8,%9}, {%0,%1,%2,%3};"
        : "+f"(c[0]), "+f"(c[1]), "+f"(c[2]), "+f"(c[3])
        : "r"(a[0]), "r"(a[1]), "r"(a[2]), "r"(a[3]), "r"(b[0]), "r"(b[1]));
}

__device__ __forceinline__ void mma_bf16(float c[4], const uint32_t a[4], const uint32_t b[2]) {
    asm volatile(
        "mma.sync.aligned.m16n8k16.row.col.f32.bf16.bf16.f32 "
        "{%0,%1,%2,%3}, {%4,%5,%6,%7}, {%8,%9}, {%0,%1,%2,%3};"
        : "+f"(c[0]), "+f"(c[1]), "+f"(c[2]), "+f"(c[3])
        : "r"(a[0]), "r"(a[1]), "r"(a[2]), "r"(a[3]), "r"(b[0]), "r"(b[1]));
}

// split (x,y) into packed bf16x2 hi and lo planes: x = hi + lo + O(2^-18 x)
__device__ __forceinline__ void split2(float x, float y, uint32_t& hi, uint32_t& lo) {
    __nv_bfloat162 h2 = __float22bfloat162_rn(make_float2(x, y));
    float2 hf = __bfloat1622float2(h2);
    __nv_bfloat162 l2 = __float22bfloat162_rn(make_float2(x - hf.x, y - hf.y));
    hi = reinterpret_cast<uint32_t&>(h2);
    lo = reinterpret_cast<uint32_t&>(l2);
}

#define CP_ASYNC16(dst, src) \
    asm volatile("cp.async.cg.shared.global [%0], [%1], 16;" :: "r"(dst), "l"(src))
#define CP_COMMIT() asm volatile("cp.async.commit_group;")
#define CP_WAIT1()  asm volatile("cp.async.wait_group 1;")

// ---------------------------------------------------------------------------
// convA: fp32 [M][K] -> tf32-rounded fp32 (elementwise, vectorized)
// ---------------------------------------------------------------------------
__global__ __launch_bounds__(256) void convA(const float* __restrict__ X,
                                             float* __restrict__ Y) {
    const int i = blockIdx.x * 256 + threadIdx.x;  // per float4
    float4 v = ((const float4*)X)[i];
    ((float4*)Y)[i] = make_float4(f2tf32(v.x), f2tf32(v.y), f2tf32(v.z), f2tf32(v.w));
}

// ---------------------------------------------------------------------------
// convW: fp32 W [GK][N] -> tf32-rounded transposed [N][GK] at row offset `off`.
// ---------------------------------------------------------------------------
__global__ __launch_bounds__(256) void convW(const float* __restrict__ W,
                                             float* __restrict__ Out,
                                             int N, int off) {
    __shared__ float ts[32][33];
    const int tid = threadIdx.x;
    const int k0 = blockIdx.y * 32, n0 = blockIdx.x * 32;
    const int r = tid >> 5, c = tid & 31;
#pragma unroll
    for (int j = 0; j < 4; j++)
        ts[j * 8 + r][c] = W[(size_t)(k0 + j * 8 + r) * N + n0 + c];
    __syncthreads();
#pragma unroll
    for (int j = 0; j < 4; j++) {
        const int n = j * 8 + r;
        Out[(size_t)(off + n0 + n) * GK + k0 + c] = f2tf32(ts[c][n]);
    }
}

// ---------------------------------------------------------------------------
// tf32 tensor-core GEMM v3: C[M,N] = A[M,K] @ B^T  (B given as [N][K]).
// A, B already tf32-rounded. BM=128, BN=256, BK=32.
// 512 threads = 16 warps (4x4), warp tile 32x64, 2x8 m16n8k8 fragments.
// 3-stage cp.async pipeline; stage = A[128][36] + B[256][36] floats (54KB).
// 16 warps/SM = 4 per SMSP for latency hiding (R13 had only 2).
// Fragment LDS banks: 4*grp + qid (+kb)  -> conflict-free.
// ---------------------------------------------------------------------------
#define GLDA 36
#define ABYTES (128 * GLDA * 4)              // 18432
#define STAGE_BYTES (384 * GLDA * 4)         // 55296  (A 128 rows + B 256 rows)
#define GEMM_SMEM   (3 * STAGE_BYTES)        // 165888

__global__ __launch_bounds__(512, 1) void gemm_v3(const float* __restrict__ A,
                                                  const float* __restrict__ B,
                                                  float* __restrict__ C,
                                                  int Ntot) {
    extern __shared__ char smem[];
    const uint32_t sb = s2u32(smem);
    const int tid = threadIdx.x;
    const int bn = blockIdx.x, bm = blockIdx.y;
    const int warp = tid >> 5, lane = tid & 31;
    const int mw = warp & 3, nw = warp >> 2;        // 4x4 warp grid
    const int grp = lane >> 2, qid = lane & 3;

    // cp.async mapping: 64 rows x 8 chunks per pass, 512 threads
    const int crow = tid >> 3;          // 0..63
    const int ccol = (tid & 7) << 4;    // byte 0..112

    const char* Ag = (const char*)(A + (size_t)(bm * 128) * GK);
    const char* Bg = (const char*)(B + (size_t)(bn * 256) * GK);

    const int T = GK / 32;  // 64 K-tiles

    auto load_stage = [&](int t, int stg) {
        const uint32_t base = sb + stg * STAGE_BYTES;
        const size_t kByte = (size_t)t * 128;
        // A: 128 rows in 2 passes
#pragma unroll
        for (int p = 0; p < 2; p++) {
            const int row = p * 64 + crow;
            CP_ASYNC16(base + row * 144 + ccol,
                       Ag + (size_t)row * (GK * 4) + kByte + ccol);
        }
        // B: 256 rows in 4 passes
#pragma unroll
        for (int p = 0; p < 4; p++) {
            const int row = p * 64 + crow;
            CP_ASYNC16(base + ABYTES + row * 144 + ccol,
                       Bg + (size_t)row * (GK * 4) + kByte + ccol);
        }
    };

    float acc[2][8][4];
#pragma unroll
    for (int mt = 0; mt < 2; mt++)
#pragma unroll
        for (int nt = 0; nt < 8; nt++)
#pragma unroll
            for (int e = 0; e < 4; e++) acc[mt][nt][e] = 0.f;

    load_stage(0, 0); CP_COMMIT();
    load_stage(1, 1); CP_COMMIT();

    for (int t = 0; t < T; t++) {
        const int stg = t % 3;
        CP_WAIT1();
        __syncthreads();

        if (t + 2 < T) load_stage(t + 2, (t + 2) % 3);
        CP_COMMIT();

        const float* As = (const float*)(smem + stg * STAGE_BYTES);
        const float* Bs = As + 128 * GLDA;

#pragma unroll
        for (int kk = 0; kk < 4; kk++) {
            const int kb = kk * 8;
            uint32_t af[2][4];
#pragma unroll
            for (int mt = 0; mt < 2; mt++) {
                const int r = mw * 32 + mt * 16 + grp;
                af[mt][0] = __float_as_uint(As[(r)     * GLDA + kb + qid]);
                af[mt][1] = __float_as_uint(As[(r + 8) * GLDA + kb + qid]);
                af[mt][2] = __float_as_uint(As[(r)     * GLDA + kb + qid + 4]);
                af[mt][3] = __float_as_uint(As[(r + 8) * GLDA + kb + qid + 4]);
            }
            uint32_t bf[8][2];
#pragma unroll
            for (int nt = 0; nt < 8; nt++) {
                const int n = nw * 64 + nt * 8 + grp;
                bf[nt][0] = __float_as_uint(Bs[n * GLDA + kb + qid]);
                bf[nt][1] = __float_as_uint(Bs[n * GLDA + kb + qid + 4]);
            }
#pragma unroll
            for (int mt = 0; mt < 2; mt++)
#pragma unroll
                for (int nt = 0; nt < 8; nt++)
                    mma_tf32(acc[mt][nt], af[mt], bf[nt]);
        }
        __syncthreads();
    }

    // epilogue: direct float2 stores
#pragma unroll
    for (int mt = 0; mt < 2; mt++) {
        const int row = bm * 128 + mw * 32 + mt * 16 + grp;
#pragma unroll
        for (int nt = 0; nt < 8; nt++) {
            const int col = bn * 256 + nw * 64 + nt * 8 + qid * 2;
            *(float2*)&C[(size_t)row * Ntot + col]       = make_float2(acc[mt][nt][0], acc[mt][nt][1]);
            *(float2*)&C[(size_t)(row + 8) * Ntot + col] = make_float2(acc[mt][nt][2], acc[mt][nt][3]);
        }
    }
}

// ---------------------------------------------------------------------------
// RoPE applied in-place to Q (heads 0..15) and K (heads 16..19) in fused QKV.
// ---------------------------------------------------------------------------
__global__ __launch_bounds__(128) void rope_kernel(float* __restrict__ QKV,
                                                   const float* __restrict__ cosp,
                                                   const float* __restrict__ sinp) {
    const int bs = blockIdx.x;
    const int hy = blockIdx.y;
    const int s  = bs & (SS - 1);

    __shared__ float x[HD];
    float* ptr;
    if (hy < HH) ptr = QKV + (size_t)bs * QKVD + hy * HD;
    else         ptr = QKV + (size_t)bs * QKVD + KOFF + (hy - HH) * HD;

    x[threadIdx.x] = ptr[threadIdx.x];
    __syncthreads();
    if (threadIdx.x < 64) {
        const int i = threadIdx.x;
        const float c  = cosp[s * 64 + i];
        const float sn = sinp[s * 64 + i];
        const float p1 = x[2 * i], p2 = x[2 * i + 1];
        ptr[i]      = p1 * c - p2 * sn;
        ptr[i + 64] = p2 * c + p1 * sn;
    }
}

// ---------------------------------------------------------------------------
// bf16x3-split tensor-core flash attention (reading fused QKV buffer).
// ---------------------------------------------------------------------------
#define FLASH_SMEM_BYTES ((2 * 64 * 68 + 2 * 128 * 36) * 4)   // 71680

__global__ __launch_bounds__(256) void flash_bf16(const float* __restrict__ QKV,
                                                  float* __restrict__ O) {
    extern __shared__ uint32_t smw[];
    uint32_t* Khi  = smw;                    // [64][68] words
    uint32_t* Klo  = smw + 64 * 68;
    uint32_t* Vthi = smw + 2 * 64 * 68;      // [128][36] words  (bf16 [128][72])
    uint32_t* Vtlo = Vthi + 128 * 36;
    __nv_bfloat16* vhs = (__nv_bfloat16*)Vthi;
    __nv_bfloat16* vls = (__nv_bfloat16*)Vtlo;

    const int bq = (int)(gridDim.x - 1) - (int)blockIdx.x;  // big tiles first
    const int h = blockIdx.y, b = blockIdx.z;
    const int kvh = h >> 2;
    const int tid = threadIdx.x, w = tid >> 5, lane = tid & 31;
    const int grp = lane >> 2, qid = lane & 3;
    const int qs = bq << 7;
    const float scale = 0.088388347648318447f;  // 1/sqrt(128)

    uint32_t qhi[8][4], qlo[8][4];
    {
        const float* q0 = QKV + (size_t)((b << 11) + qs + (w << 4) + grp) * QKVD + (h << 7);
        const float* q1 = q0 + (size_t)8 * QKVD;
#pragma unroll
        for (int kk = 0; kk < 8; kk++) {
            const int c = (kk << 4) + (qid << 1);
            float2 x0 = *(const float2*)(q0 + c);
            float2 x1 = *(const float2*)(q1 + c);
            float2 x2 = *(const float2*)(q0 + c + 8);
            float2 x3 = *(const float2*)(q1 + c + 8);
            split2(x0.x * scale, x0.y * scale, qhi[kk][0], qlo[kk][0]);
            split2(x1.x * scale, x1.y * scale, qhi[kk][1], qlo[kk][1]);
            split2(x2.x * scale, x2.y * scale, qhi[kk][2], qlo[kk][2]);
            split2(x3.x * scale, x3.y * scale, qhi[kk][3], qlo[kk][3]);
        }
    }

    float oacc[16][4];
#pragma unroll
    for (int f = 0; f < 16; f++)
#pragma unroll
        for (int e = 0; e < 4; e++) oacc[f][e] = 0.f;
    float m0 = -1e30f, m1 = -1e30f, l0 = 0.f, l1 = 0.f;

    const int ntiles = (bq << 1) + 2;
    for (int t = 0; t < ntiles; t++) {
        const int ks = t << 6;
        __syncthreads();

        for (int idx = tid; idx < 64 * 32; idx += 256) {
            const int key = idx >> 5, mm = idx & 31;
            float4 kv = *(const float4*)(QKV + (size_t)((b << 11) + ks + key) * QKVD + KOFF + (kvh << 7) + (mm << 2));
            uint32_t h0, w0, h1, w1;
            split2(kv.x, kv.y, h0, w0);
            split2(kv.z, kv.w, h1, w1);
            Khi[key * 68 + 2 * mm]     = h0;
            Khi[key * 68 + 2 * mm + 1] = h1;
            Klo[key * 68 + 2 * mm]     = w0;
            Klo[key * 68 + 2 * mm + 1] = w1;
        }
        for (int idx = tid; idx < 64 * 32; idx += 256) {
            const int key = idx & 63, dm = idx >> 6;
            const int d4 = dm << 2;
            float4 vv = *(const float4*)(QKV + (size_t)((b << 11) + ks + key) * QKVD + VOFF + (kvh << 7) + d4);
            float vals[4] = {vv.x, vv.y, vv.z, vv.w};
#pragma unroll
            for (int j = 0; j < 4; j++) {
                __nv_bfloat16 hb = __float2bfloat16_rn(vals[j]);
                float r = vals[j] - __bfloat162float(hb);
                vhs[(d4 + j) * 72 + key] = hb;
                vls[(d4 + j) * 72 + key] = __float2bfloat16_rn(r);
            }
        }
        __syncthreads();

        float sacc[8][4];
#pragma unroll
        for (int nf = 0; nf < 8; nf++)
#pragma unroll
            for (int e = 0; e < 4; e++) sacc[nf][e] = 0.f;

#pragma unroll
        for (int kk = 0; kk < 8; kk++) {
#pragma unroll
            for (int nf = 0; nf < 8; nf++) {
                const int base = (nf * 8 + grp) * 68 + kk * 8 + qid;
                uint32_t bh[2] = {Khi[base], Khi[base + 4]};
                uint32_t bl[2] = {Klo[base], Klo[base + 4]};
                mma_bf16(sacc[nf], qhi[kk], bh);
                mma_bf16(sacc[nf], qhi[kk], bl);
                mma_bf16(sacc[nf], qlo[kk], bh);
            }
        }

        if (t >= (bq << 1)) {
            const int g0 = qs + (w << 4) + grp, g1 = g0 + 8;
#pragma unroll
            for (int nf = 0; nf < 8; nf++) {
                const int k0 = ks + nf * 8 + (qid << 1);
                if (k0     > g0) sacc[nf][0] = -1e30f;
                if (k0 + 1 > g0) sacc[nf][1] = -1e30f;
                if (k0     > g1) sacc[nf][2] = -1e30f;
                if (k0 + 1 > g1) sacc[nf][3] = -1e30f;
            }
        }

        float mx0 = -1e30f, mx1 = -1e30f;
#pragma unroll
        for (int nf = 0; nf < 8; nf++) {
            mx0 = fmaxf(mx0, fmaxf(sacc[nf][0], sacc[nf][1]));
            mx1 = fmaxf(mx1, fmaxf(sacc[nf][2], sacc[nf][3]));
        }
        mx0 = fmaxf(mx0, __shfl_xor_sync(0xffffffffu, mx0, 1));
        mx0 = fmaxf(mx0, __shfl_xor_sync(0xffffffffu, mx0, 2));
        mx1 = fmaxf(mx1, __shfl_xor_sync(0xffffffffu, mx1, 1));
        mx1 = fmaxf(mx1, __shfl_xor_sync(0xffffffffu, mx1, 2));
        const float mn0 = fmaxf(m0, mx0), mn1 = fmaxf(m1, mx1);
        const float a0 = __expf(m0 - mn0), a1 = __expf(m1 - mn1);
        float s0 = 0.f, s1 = 0.f;
#pragma unroll
        for (int nf = 0; nf < 8; nf++) {
            sacc[nf][0] = __expf(sacc[nf][0] - mn0);
            sacc[nf][1] = __expf(sacc[nf][1] - mn0);
            sacc[nf][2] = __expf(sacc[nf][2] - mn1);
            sacc[nf][3] = __expf(sacc[nf][3] - mn1);
            s0 += sacc[nf][0] + sacc[nf][1];
            s1 += sacc[nf][2] + sacc[nf][3];
        }
        s0 += __shfl_xor_sync(0xffffffffu, s0, 1);
        s0 += __shfl_xor_sync(0xffffffffu, s0, 2);
        s1 += __shfl_xor_sync(0xffffffffu, s1, 1);
        s1 += __shfl_xor_sync(0xffffffffu, s1, 2);
        l0 = l0 * a0 + s0;
        l1 = l1 * a1 + s1;
        m0 = mn0; m1 = mn1;
#pragma unroll
        for (int f = 0; f < 16; f++) {
            oacc[f][0] *= a0; oacc[f][1] *= a0;
            oacc[f][2] *= a1; oacc[f][3] *= a1;
        }

        uint32_t pah[8], pal[8], pbh[8], pbl[8];
#pragma unroll
        for (int nf = 0; nf < 8; nf++) {
            split2(sacc[nf][0], sacc[nf][1], pah[nf], pal[nf]);
            split2(sacc[nf][2], sacc[nf][3], pbh[nf], pbl[nf]);
        }

#pragma unroll
        for (int kk = 0; kk < 4; kk++) {
            uint32_t ah[4] = {pah[2 * kk], pbh[2 * kk], pah[2 * kk + 1], pbh[2 * kk + 1]};
            uint32_t al[4] = {pal[2 * kk], pbl[2 * kk], pal[2 * kk + 1], pbl[2 * kk + 1]};
#pragma unroll
            for (int nf = 0; nf < 16; nf++) {
                const int base = (nf * 8 + grp) * 36 + kk * 8 + qid;
                uint32_t bh[2] = {Vthi[base], Vthi[base + 4]};
                uint32_t bl[2] = {Vtlo[base], Vtlo[base + 4]};
                mma_bf16(oacc[nf], ah, bh);
                mma_bf16(oacc[nf], ah, bl);
                mma_bf16(oacc[nf], al, bh);
            }
        }
    }

    const float i0 = 1.0f / l0, i1 = 1.0f / l1;
    float* o0 = O + (size_t)((b << 11) + qs + (w << 4) + grp) * DD + (h << 7);
    float* o1 = o0 + (size_t)8 * DD;
#pragma unroll
    for (int nf = 0; nf < 16; nf++) {
        const int col = nf * 8 + (qid << 1);
        *(float2*)(o0 + col) = make_float2(oacc[nf][0] * i0, oacc[nf][1] * i0);
        *(float2*)(o1 + col) = make_float2(oacc[nf][2] * i1, oacc[nf][3] * i1);
    }
}

// ---------------------------------------------------------------------------
extern "C" void kernel_launch(void* const* d_in, const int* in_sizes, int n_in,
                              void* d_out, int out_size) {
    const float* hidden = (const float*)d_in[0];
    // d_in[1] = attention_mask (pure causal; handled analytically)
    const float* cosp = (const float*)d_in[2];
    const float* sinp = (const float*)d_in[3];
    const float* Wq   = (const float*)d_in[4];
    const float* Wk   = (const float*)d_in[5];
    const float* Wv   = (const float*)d_in[6];
    const float* Wo   = (const float*)d_in[7];
    float* out = (float*)d_out;

    float *QKVb, *Ob, *Af, *Bt;
    cudaGetSymbolAddress((void**)&QKVb, g_QKV);
    cudaGetSymbolAddress((void**)&Ob, g_O);
    cudaGetSymbolAddress((void**)&Af, g_Af);
    cudaGetSymbolAddress((void**)&Bt, g_Bt);

    cudaFuncSetAttribute(flash_bf16, cudaFuncAttributeMaxDynamicSharedMemorySize, FLASH_SMEM_BYTES);
    cudaFuncSetAttribute(gemm_v3, cudaFuncAttributeMaxDynamicSharedMemorySize, GEMM_SMEM);

    const int convA_blocks = (MROWS * GK) / 4 / 256;  // 8192

    // ---- fused QKV projection ----
    convA<<<convA_blocks, 256>>>(hidden, Af);
    convW<<<dim3(DD / 32,  GK / 32), 256>>>(Wq, Bt, DD,  0);
    convW<<<dim3(KVD / 32, GK / 32), 256>>>(Wk, Bt, KVD, KOFF);
    convW<<<dim3(KVD / 32, GK / 32), 256>>>(Wv, Bt, KVD, VOFF);
    gemm_v3<<<dim3(QKVD / 256, MROWS / 128), 512, GEMM_SMEM>>>(Af, Bt, QKVb, QKVD);
    // ---- RoPE on Q and K (in place) ----
    rope_kernel<<<dim3(MROWS, HH + KVH), 128>>>(QKVb, cosp, sinp);
    // ---- causal flash attention (bf16x3-split tensor cores) ----
    flash_bf16<<<dim3(SS / 128, HH, BB), 256, FLASH_SMEM_BYTES>>>(QKVb, Ob);
    // ---- output projection ----
    convA<<<convA_blocks, 256>>>(Ob, Af);
    convW<<<dim3(DD / 32, GK / 32), 256>>>(Wo, Bt, DD, 0);
    gemm_v3<<<dim3(DD / 256, MROWS / 128), 512, GEMM_SMEM>>>(Af, Bt, out, DD);
}